// round 15
// baseline (speedup 1.0000x reference)
#include <cuda_runtime.h>
#include <cuda_fp16.h>
#include <math.h>
#include <cstdint>

#define D_MODEL 1024
#define T_SEQ   2048
#define BATCH   2
#define NTOK    (BATCH * T_SEQ)   // 4096
#define D_FF    4096
#define NH      16
#define DH      64
#define QKV_N   3072

// ---------------- scratch (no allocations allowed) ----------------
__device__ __half g_xn_h  [NTOK * D_MODEL];
__device__ __half g_qkv_h [NTOK * QKV_N];
__device__ __half g_attn_h[NTOK * D_MODEL];
__device__ float  g_x2    [NTOK * D_MODEL];
__device__ __half g_hn_h  [NTOK * D_MODEL];
__device__ __half g_f1_h  [NTOK * D_FF];
__device__ __half g_wqkvT [QKV_N * D_MODEL];
__device__ __half g_woT   [D_MODEL * D_MODEL];
__device__ __half g_w1T   [D_FF * D_MODEL];
__device__ __half g_w2T   [D_MODEL * D_FF];

__device__ __forceinline__ uint32_t smem_u32(const void* p) {
    uint32_t a;
    asm("{ .reg .u64 t; cvta.to.shared.u64 t, %1; cvt.u32.u64 %0, t; }" : "=r"(a) : "l"(p));
    return a;
}
#define CP_ASYNC16(dst, src) \
    asm volatile("cp.async.cg.shared.global [%0], [%1], 16;" :: "r"(dst), "l"(src))
#define CP_COMMIT() asm volatile("cp.async.commit_group;")
#define CP_WAIT0()  asm volatile("cp.async.wait_group 0;")
#define CP_WAIT1()  asm volatile("cp.async.wait_group 1;")

#define MMA_F16(c0, c1, c2, c3, a0, a1, a2, a3, b0, b1) \
    asm volatile( \
        "mma.sync.aligned.m16n8k16.row.col.f32.f16.f16.f32 " \
        "{%0,%1,%2,%3}, {%4,%5,%6,%7}, {%8,%9}, {%0,%1,%2,%3};" \
        : "+f"(c0), "+f"(c1), "+f"(c2), "+f"(c3) \
        : "r"(a0), "r"(a1), "r"(a2), "r"(a3), "r"(b0), "r"(b1))

// fp16-accumulate variant (2x rate); acc packed {c0,c1},{c2,c3} as half2
#define MMA_F16H(cc0, cc1, a0, a1, a2, a3, b0, b1) \
    asm volatile( \
        "mma.sync.aligned.m16n8k16.row.col.f16.f16.f16.f16 " \
        "{%0,%1}, {%2,%3,%4,%5}, {%6,%7}, {%0,%1};" \
        : "+r"(cc0), "+r"(cc1) \
        : "r"(a0), "r"(a1), "r"(a2), "r"(a3), "r"(b0), "r"(b1))

#define LDSM4(r0, r1, r2, r3, a) \
    asm volatile("ldmatrix.sync.aligned.m8n8.x4.shared.b16 {%0,%1,%2,%3}, [%4];" \
        : "=r"(r0), "=r"(r1), "=r"(r2), "=r"(r3) : "r"(a))
#define LDSM4T(r0, r1, r2, r3, a) \
    asm volatile("ldmatrix.sync.aligned.m8n8.x4.trans.shared.b16 {%0,%1,%2,%3}, [%4];" \
        : "=r"(r0), "=r"(r1), "=r"(r2), "=r"(r3) : "r"(a))

// ---------------- weight transposes: W[K][N] -> WT[N][K] (fp16) ----------------
__device__ __forceinline__ void trans_tile(
    const float* __restrict__ W, __half* __restrict__ WT, int K, int N, int n0, int k0)
{
    __shared__ float t[32][33];
    int tx = threadIdx.x & 31, ty = threadIdx.x >> 5;   // 32x8
    #pragma unroll
    for (int i = 0; i < 32; i += 8)
        t[ty + i][tx] = W[(size_t)(k0 + ty + i) * N + n0 + tx];
    __syncthreads();
    #pragma unroll
    for (int i = 0; i < 32; i += 8)
        WT[(size_t)(n0 + ty + i) * K + k0 + tx] = __float2half_rn(t[tx][ty + i]);
}

__global__ void __launch_bounds__(256) transpose_qkvw(
    const float* __restrict__ Wq, const float* __restrict__ Wk,
    const float* __restrict__ Wv, __half* __restrict__ qkvT)
{
    int z = blockIdx.z;
    const float* src = (z == 0) ? Wq : (z == 1) ? Wk : Wv;
    trans_tile(src, qkvT + (size_t)z * D_MODEL * D_MODEL,
               D_MODEL, D_MODEL, blockIdx.x * 32, blockIdx.y * 32);
}

__global__ void __launch_bounds__(256) transpose_wo(
    const float* __restrict__ Wo, __half* __restrict__ woT)
{
    trans_tile(Wo, woT, D_MODEL, D_MODEL, blockIdx.x * 32, blockIdx.y * 32);
}

__global__ void __launch_bounds__(256) transpose_ffn(
    const float* __restrict__ W1, const float* __restrict__ W2,
    __half* __restrict__ w1T, __half* __restrict__ w2T)
{
    if (blockIdx.z == 0)
        trans_tile(W1, w1T, D_MODEL, D_FF, blockIdx.x * 32, blockIdx.y * 32);
    else
        trans_tile(W2, w2T, D_FF, D_MODEL, blockIdx.y * 32, blockIdx.x * 32);
}

// ---------------- RMSNorm (R13 block-per-row version — best measured) ----------------
__global__ void __launch_bounds__(256) rmsnorm_h(
    const float* __restrict__ x, const float* __restrict__ g, __half* __restrict__ y)
{
    int row = blockIdx.x;
    int tid = threadIdx.x;
    const float4* xr = (const float4*)(x + (size_t)row * D_MODEL);
    float4 v = xr[tid];
    float s = v.x * v.x + v.y * v.y + v.z * v.z + v.w * v.w;
    #pragma unroll
    for (int o = 16; o > 0; o >>= 1) s += __shfl_xor_sync(0xffffffffu, s, o);
    __shared__ float red[8];
    if ((tid & 31) == 0) red[tid >> 5] = s;
    __syncthreads();
    float tot = red[0] + red[1] + red[2] + red[3] + red[4] + red[5] + red[6] + red[7];
    float inv = rsqrtf(tot * (1.0f / D_MODEL) + 1e-6f);
    float4 gv = ((const float4*)g)[tid];
    __half2* yp = (__half2*)(y + (size_t)row * D_MODEL + tid * 4);
    yp[0] = __floats2half2_rn(v.x * inv * gv.x, v.y * inv * gv.y);
    yp[1] = __floats2half2_rn(v.z * inv * gv.z, v.w * inv * gv.w);
}

// ---------------- fp16 mma GEMM: R8 winner (3-stage cp.async + reg-pipelined frags) ----------
#define KC 64
#define HSTR 72
#define STAGE_HL (128 * HSTR)
#define STAGE_B  (STAGE_HL * 2)          // 18,432 bytes
#define GEMM_SMEM (3 * 2 * STAGE_B)      // 110,592 bytes

template<bool BIAS, bool GELU_ACT, bool RES, bool HOUT>
__global__ void __launch_bounds__(256) gemm_h(
    const __half* __restrict__ A, const __half* __restrict__ BT,
    const float* __restrict__ bias, const float* __restrict__ res,
    void* __restrict__ Cv, int M, int N, int K)
{
    extern __shared__ __half smh[];
    uint32_t AsU = smem_u32(smh);
    uint32_t BsU = AsU + 3 * STAGE_B;

    int tid = threadIdx.x;
    int lane = tid & 31, wid = tid >> 5;
    int warpM = (wid & 1) * 64;
    int warpN = (wid >> 1) * 32;
    int grp = lane >> 2, tig = lane & 3;
    int m8 = lane >> 3, l8 = lane & 7;
    int bn = blockIdx.x, bm = blockIdx.y;

    int ldrow = tid >> 3;                // 0..31, step 32
    int ldseg = (tid & 7) << 3;          // 0..56 halfs
    const __half* Aptr = A  + (size_t)bm * 128 * K + (size_t)ldrow * K + ldseg;
    const __half* Bptr = BT + (size_t)bn * 128 * K + (size_t)ldrow * K + ldseg;
    uint32_t dA = AsU + (uint32_t)(ldrow * HSTR + ldseg) * 2;
    uint32_t dB = BsU + (uint32_t)(ldrow * HSTR + ldseg) * 2;

    uint32_t aOff[4], bOff[2];
    #pragma unroll
    for (int mi = 0; mi < 4; mi++)
        aOff[mi] = (uint32_t)((warpM + mi * 16 + (lane & 15)) * HSTR
                              + ((lane >> 4) << 3)) * 2;
    #pragma unroll
    for (int j = 0; j < 2; j++)
        bOff[j] = (uint32_t)((warpN + j * 16 + ((m8 >> 1) << 3) + l8) * HSTR
                              + ((m8 & 1) << 3)) * 2;

    float acc[4][4][4];
    #pragma unroll
    for (int mi = 0; mi < 4; mi++)
        #pragma unroll
        for (int ni = 0; ni < 4; ni++)
            #pragma unroll
            for (int r = 0; r < 4; r++) acc[mi][ni][r] = 0.f;

    int nch = K / KC;

    #pragma unroll
    for (int s = 0; s < 2; s++) {
        uint32_t so = (uint32_t)s * STAGE_B;
        int k0 = s * KC;
        #pragma unroll
        for (int t = 0; t < 4; t++) {
            CP_ASYNC16(dA + so + (uint32_t)(t * 32 * HSTR) * 2,
                       Aptr + (size_t)t * 32 * K + k0);
            CP_ASYNC16(dB + so + (uint32_t)(t * 32 * HSTR) * 2,
                       Bptr + (size_t)t * 32 * K + k0);
        }
        CP_COMMIT();
    }

    uint32_t af[2][4][4], bf[2][4][2];

    int stage = 0;
    for (int c = 0; c < nch; c++) {
        if (c + 1 < nch) { CP_WAIT1(); } else { CP_WAIT0(); }
        __syncthreads();
        if (c + 2 < nch) {
            int sn = stage - 1; if (sn < 0) sn += 3;
            uint32_t so = (uint32_t)sn * STAGE_B;
            int k0 = (c + 2) * KC;
            #pragma unroll
            for (int t = 0; t < 4; t++) {
                CP_ASYNC16(dA + so + (uint32_t)(t * 32 * HSTR) * 2,
                           Aptr + (size_t)t * 32 * K + k0);
                CP_ASYNC16(dB + so + (uint32_t)(t * 32 * HSTR) * 2,
                           Bptr + (size_t)t * 32 * K + k0);
            }
            CP_COMMIT();
        }
        uint32_t abase = AsU + (uint32_t)stage * STAGE_B;
        uint32_t bbase = BsU + (uint32_t)stage * STAGE_B;

        #pragma unroll
        for (int mi = 0; mi < 4; mi++)
            LDSM4(af[0][mi][0], af[0][mi][1], af[0][mi][2], af[0][mi][3],
                  abase + aOff[mi]);
        #pragma unroll
        for (int j = 0; j < 2; j++)
            LDSM4(bf[0][2 * j][0], bf[0][2 * j][1], bf[0][2 * j + 1][0], bf[0][2 * j + 1][1],
                  bbase + bOff[j]);

        #pragma unroll
        for (int kk = 0; kk < 4; kk++) {
            int cur = kk & 1, nxt = cur ^ 1;
            if (kk < 3) {
                uint32_t kb = (uint32_t)(kk + 1) * 32;
                #pragma unroll
                for (int mi = 0; mi < 4; mi++)
                    LDSM4(af[nxt][mi][0], af[nxt][mi][1], af[nxt][mi][2], af[nxt][mi][3],
                          abase + aOff[mi] + kb);
                #pragma unroll
                for (int j = 0; j < 2; j++)
                    LDSM4(bf[nxt][2 * j][0], bf[nxt][2 * j][1],
                          bf[nxt][2 * j + 1][0], bf[nxt][2 * j + 1][1],
                          bbase + bOff[j] + kb);
            }
            #pragma unroll
            for (int mi = 0; mi < 4; mi++)
                #pragma unroll
                for (int ni = 0; ni < 4; ni++)
                    MMA_F16(acc[mi][ni][0], acc[mi][ni][1], acc[mi][ni][2], acc[mi][ni][3],
                            af[cur][mi][0], af[cur][mi][1], af[cur][mi][2], af[cur][mi][3],
                            bf[cur][ni][0], bf[cur][ni][1]);
        }
        stage++; if (stage == 3) stage = 0;
    }

    #pragma unroll
    for (int mi = 0; mi < 4; mi++) {
        #pragma unroll
        for (int half = 0; half < 2; half++) {
            size_t r = (size_t)bm * 128 + warpM + mi * 16 + grp + half * 8;
            #pragma unroll
            for (int ni = 0; ni < 4; ni++) {
                int cg = bn * 128 + warpN + ni * 8 + tig * 2;
                float v0 = acc[mi][ni][half * 2 + 0];
                float v1 = acc[mi][ni][half * 2 + 1];
                if (BIAS) { v0 += bias[cg]; v1 += bias[cg + 1]; }
                if (GELU_ACT) {
                    v0 = 0.5f * v0 * (1.0f + erff(v0 * 0.70710678118654752f));
                    v1 = 0.5f * v1 * (1.0f + erff(v1 * 0.70710678118654752f));
                }
                size_t idx = r * (size_t)N + cg;
                if (RES) {
                    float2 r2 = *(const float2*)(res + idx);
                    v0 += r2.x; v1 += r2.y;
                }
                if (HOUT) {
                    *(__half2*)((__half*)Cv + idx) = __floats2half2_rn(v0, v1);
                } else {
                    float2 o2; o2.x = v0; o2.y = v1;
                    *(float2*)((float*)Cv + idx) = o2;
                }
            }
        }
    }
}

// ---------------- fp16 mma causal flash attention (f16-acc QK, base-2 softmax) ----------------
#define ASTR 72
#define Q_HL (64 * ASTR)
#define K_HL (64 * ASTR)
#define V_HL (64 * ASTR)
#define P_HL (16 * ASTR)
#define ATTN_SMEM ((Q_HL + 2 * K_HL + 2 * V_HL + 4 * P_HL) * 2)
#define SCL2 0.18033688011112042f   // 0.125 * log2(e)

__global__ void __launch_bounds__(128) attn_h(
    const __half* __restrict__ qkv, __half* __restrict__ o)
{
    extern __shared__ __half smh[];
    __half* Qs = smh;
    __half* Ks = Qs + Q_HL;           // 2 buffers
    __half* Vs = Ks + 2 * K_HL;       // 2 buffers
    int tid = threadIdx.x;
    int lane = tid & 31, wid = tid >> 5;
    int grp = lane >> 2, tig = lane & 3;
    int m8 = lane >> 3, l8 = lane & 7;
    __half* Ps = Vs + 2 * V_HL + wid * P_HL;

    uint32_t QsU = smem_u32(Qs), KsU = smem_u32(Ks), VsU = smem_u32(Vs);
    uint32_t PsU = smem_u32(Ps);

    int qb = gridDim.x - 1 - blockIdx.x;   // heavy tiles first
    int h = blockIdx.y, b = blockIdx.z;
    size_t base  = (size_t)b * T_SEQ * QKV_N + h * DH;
    size_t baseo = (size_t)b * T_SEQ * D_MODEL + h * DH;
    const __half* qg = qkv + base;
    const __half* kg = qkv + base + D_MODEL;
    const __half* vg = qkv + base + 2 * D_MODEL;

    uint32_t qOff = (uint32_t)((wid * 16 + (lane & 15)) * ASTR + ((lane >> 4) << 3)) * 2;
    uint32_t kOff[4], vOff[4];
    #pragma unroll
    for (int j = 0; j < 4; j++) {
        kOff[j] = (uint32_t)((j * 16 + ((m8 >> 1) << 3) + l8) * ASTR
                             + ((m8 & 1) << 3)) * 2;
        vOff[j] = (uint32_t)((((m8 & 1) << 3) + l8) * ASTR
                             + j * 16 + ((m8 >> 1) << 3)) * 2;
    }
    uint32_t pOff = (uint32_t)((lane & 15) * ASTR + ((lane >> 4) << 3)) * 2;

    int ldrow = tid >> 3, ldseg = (tid & 7) << 3;   // 16 rows/step

    #pragma unroll
    for (int t = 0; t < 4; t++) {
        int r = ldrow + t * 16;
        CP_ASYNC16(QsU + (uint32_t)(r * ASTR + ldseg) * 2,
                   qg + (size_t)(qb * 64 + r) * QKV_N + ldseg);
    }
    #pragma unroll
    for (int t = 0; t < 4; t++) {
        int r = ldrow + t * 16;
        CP_ASYNC16(KsU + (uint32_t)(r * ASTR + ldseg) * 2, kg + (size_t)r * QKV_N + ldseg);
        CP_ASYNC16(VsU + (uint32_t)(r * ASTR + ldseg) * 2, vg + (size_t)r * QKV_N + ldseg);
    }
    CP_COMMIT();

    float m0 = -1e30f, m1 = -1e30f, l0 = 0.f, l1 = 0.f;
    float oa[8][4];
    #pragma unroll
    for (int ni = 0; ni < 8; ni++)
        #pragma unroll
        for (int r = 0; r < 4; r++) oa[ni][r] = 0.f;

    int row_l0 = wid * 16 + grp;
    int row_l1 = row_l0 + 8;

    for (int kb = 0; kb <= qb; kb++) {
        CP_WAIT0();
        __syncthreads();
        if (kb < qb) {
            uint32_t kbuf = KsU + (uint32_t)(((kb + 1) & 1) * K_HL) * 2;
            uint32_t vbuf = VsU + (uint32_t)(((kb + 1) & 1) * V_HL) * 2;
            const __half* kgn = kg + (size_t)(kb + 1) * 64 * QKV_N;
            const __half* vgn = vg + (size_t)(kb + 1) * 64 * QKV_N;
            #pragma unroll
            for (int t = 0; t < 4; t++) {
                int r = ldrow + t * 16;
                CP_ASYNC16(kbuf + (uint32_t)(r * ASTR + ldseg) * 2,
                           kgn + (size_t)r * QKV_N + ldseg);
                CP_ASYNC16(vbuf + (uint32_t)(r * ASTR + ldseg) * 2,
                           vgn + (size_t)r * QKV_N + ldseg);
            }
            CP_COMMIT();
        }
        uint32_t kcur = KsU + (uint32_t)((kb & 1) * K_HL) * 2;
        uint32_t vcur = VsU + (uint32_t)((kb & 1) * V_HL) * 2;

        // S = Q @ K^T  (fp16 accumulate, 2x rate; K=64 -> only 4 roundings)
        uint32_t sh[8][2];
        #pragma unroll
        for (int ni = 0; ni < 8; ni++) { sh[ni][0] = 0u; sh[ni][1] = 0u; }
        #pragma unroll
        for (int ks = 0; ks < 4; ks++) {
            uint32_t kbyte = (uint32_t)ks * 32;
            uint32_t a0, a1, a2, a3;
            LDSM4(a0, a1, a2, a3, QsU + qOff + kbyte);
            uint32_t bfr[8][2];
            #pragma unroll
            for (int j = 0; j < 4; j++)
                LDSM4(bfr[2 * j][0], bfr[2 * j][1], bfr[2 * j + 1][0], bfr[2 * j + 1][1],
                      kcur + kOff[j] + kbyte);
            #pragma unroll
            for (int ni = 0; ni < 8; ni++)
                MMA_F16H(sh[ni][0], sh[ni][1],
                         a0, a1, a2, a3, bfr[ni][0], bfr[ni][1]);
        }
        // unpack to fp32 and scale into base-2 domain
        float s[8][4];
        #pragma unroll
        for (int ni = 0; ni < 8; ni++) {
            float2 f01 = __half22float2(*(__half2*)&sh[ni][0]);
            float2 f23 = __half22float2(*(__half2*)&sh[ni][1]);
            s[ni][0] = f01.x * SCL2; s[ni][1] = f01.y * SCL2;
            s[ni][2] = f23.x * SCL2; s[ni][3] = f23.y * SCL2;
        }
        if (kb == qb) {
            #pragma unroll
            for (int ni = 0; ni < 8; ni++) {
                int c0 = ni * 8 + tig * 2, c1 = c0 + 1;
                if (c0 > row_l0) s[ni][0] = -1e30f;
                if (c1 > row_l0) s[ni][1] = -1e30f;
                if (c0 > row_l1) s[ni][2] = -1e30f;
                if (c1 > row_l1) s[ni][3] = -1e30f;
            }
        }

        float rm0 = -1e30f, rm1 = -1e30f;
        #pragma unroll
        for (int ni = 0; ni < 8; ni++) {
            rm0 = fmaxf(rm0, fmaxf(s[ni][0], s[ni][1]));
            rm1 = fmaxf(rm1, fmaxf(s[ni][2], s[ni][3]));
        }
        rm0 = fmaxf(rm0, __shfl_xor_sync(0xffffffffu, rm0, 1));
        rm0 = fmaxf(rm0, __shfl_xor_sync(0xffffffffu, rm0, 2));
        rm1 = fmaxf(rm1, __shfl_xor_sync(0xffffffffu, rm1, 1));
        rm1 = fmaxf(rm1, __shfl_xor_sync(0xffffffffu, rm1, 2));
        float mn0 = fmaxf(m0, rm0), mn1 = fmaxf(m1, rm1);
        float al0 = exp2f(m0 - mn0), al1 = exp2f(m1 - mn1);
        float rs0 = 0.f, rs1 = 0.f;
        #pragma unroll
        for (int ni = 0; ni < 8; ni++) {
            s[ni][0] = exp2f(s[ni][0] - mn0); rs0 += s[ni][0];
            s[ni][1] = exp2f(s[ni][1] - mn0); rs0 += s[ni][1];
            s[ni][2] = exp2f(s[ni][2] - mn1); rs1 += s[ni][2];
            s[ni][3] = exp2f(s[ni][3] - mn1); rs1 += s[ni][3];
        }
        rs0 += __shfl_xor_sync(0xffffffffu, rs0, 1);
        rs0 += __shfl_xor_sync(0xffffffffu, rs0, 2);
        rs1 += __shfl_xor_sync(0xffffffffu, rs1, 1);
        rs1 += __shfl_xor_sync(0xffffffffu, rs1, 2);
        l0 = l0 * al0 + rs0; l1 = l1 * al1 + rs1;
        m0 = mn0; m1 = mn1;
        #pragma unroll
        for (int ni = 0; ni < 8; ni++) {
            oa[ni][0] *= al0; oa[ni][1] *= al0;
            oa[ni][2] *= al1; oa[ni][3] *= al1;
        }

        #pragma unroll
        for (int ni = 0; ni < 8; ni++) {
            int cc = ni * 8 + tig * 2;
            *(__half2*)(Ps + grp * ASTR + cc)       = __floats2half2_rn(s[ni][0], s[ni][1]);
            *(__half2*)(Ps + (grp + 8) * ASTR + cc) = __floats2half2_rn(s[ni][2], s[ni][3]);
        }
        __syncwarp();

        #pragma unroll
        for (int ks = 0; ks < 4; ks++) {
            uint32_t a0, a1, a2, a3;
            LDSM4(a0, a1, a2, a3, PsU + pOff + (uint32_t)ks * 32);
            uint32_t vrow = (uint32_t)(ks * 16 * ASTR) * 2;
            uint32_t bfr[8][2];
            #pragma unroll
            for (int j = 0; j < 4; j++)
                LDSM4T(bfr[2 * j][0], bfr[2 * j][1], bfr[2 * j + 1][0], bfr[2 * j + 1][1],
                       vcur + vrow + vOff[j]);
            #pragma unroll
            for (int ni = 0; ni < 8; ni++)
                MMA_F16(oa[ni][0], oa[ni][1], oa[ni][2], oa[ni][3],
                        a0, a1, a2, a3, bfr[ni][0], bfr[ni][1]);
        }
        __syncwarp();
    }

    float inv0 = 1.f / l0, inv1 = 1.f / l1;
    size_t r0 = baseo + (size_t)(qb * 64 + row_l0) * D_MODEL;
    size_t r1 = baseo + (size_t)(qb * 64 + row_l1) * D_MODEL;
    #pragma unroll
    for (int ni = 0; ni < 8; ni++) {
        int cc = ni * 8 + tig * 2;
        *(__half2*)(o + r0 + cc) = __floats2half2_rn(oa[ni][0] * inv0, oa[ni][1] * inv0);
        *(__half2*)(o + r1 + cc) = __floats2half2_rn(oa[ni][2] * inv1, oa[ni][3] * inv1);
    }
}

// ---------------- launch (dual-stream: transposes overlap the activation chain) --------
extern "C" void kernel_launch(void* const* d_in, const int* in_sizes, int n_in,
                              void* d_out, int out_size)
{
    const float* x  = (const float*)d_in[0];
    const float* Wq = (const float*)d_in[1];
    const float* Wk = (const float*)d_in[2];
    const float* Wv = (const float*)d_in[3];
    const float* Wo = (const float*)d_in[4];
    const float* W1 = (const float*)d_in[5];
    const float* b1 = (const float*)d_in[6];
    const float* W2 = (const float*)d_in[7];
    const float* b2 = (const float*)d_in[8];
    const float* g1 = (const float*)d_in[9];
    const float* g2 = (const float*)d_in[10];
    float* out = (float*)d_out;

    __half *xn, *qkv, *attn, *hn, *f1, *wqkvT, *woT, *w1T, *w2T;
    float* x2;
    cudaGetSymbolAddress((void**)&xn,    g_xn_h);
    cudaGetSymbolAddress((void**)&qkv,   g_qkv_h);
    cudaGetSymbolAddress((void**)&attn,  g_attn_h);
    cudaGetSymbolAddress((void**)&x2,    g_x2);
    cudaGetSymbolAddress((void**)&hn,    g_hn_h);
    cudaGetSymbolAddress((void**)&f1,    g_f1_h);
    cudaGetSymbolAddress((void**)&wqkvT, g_wqkvT);
    cudaGetSymbolAddress((void**)&woT,   g_woT);
    cudaGetSymbolAddress((void**)&w1T,   g_w1T);
    cudaGetSymbolAddress((void**)&w2T,   g_w2T);

    cudaFuncSetAttribute(gemm_h<false, false, false, true>,
                         cudaFuncAttributeMaxDynamicSharedMemorySize, GEMM_SMEM);
    cudaFuncSetAttribute(gemm_h<false, false, true, false>,
                         cudaFuncAttributeMaxDynamicSharedMemorySize, GEMM_SMEM);
    cudaFuncSetAttribute(gemm_h<true, true, false, true>,
                         cudaFuncAttributeMaxDynamicSharedMemorySize, GEMM_SMEM);
    cudaFuncSetAttribute(gemm_h<true, false, true, false>,
                         cudaFuncAttributeMaxDynamicSharedMemorySize, GEMM_SMEM);
    cudaFuncSetAttribute(attn_h, cudaFuncAttributeMaxDynamicSharedMemorySize, ATTN_SMEM);

    // static side-stream + events (created on the first, uncaptured, call)
    static cudaStream_t s1 = nullptr;
    static cudaEvent_t evRoot = nullptr, evQkvW = nullptr, evRestW = nullptr;
    if (!s1) {
        cudaStreamCreateWithFlags(&s1, cudaStreamNonBlocking);
        cudaEventCreateWithFlags(&evRoot,  cudaEventDisableTiming);
        cudaEventCreateWithFlags(&evQkvW,  cudaEventDisableTiming);
        cudaEventCreateWithFlags(&evRestW, cudaEventDisableTiming);
    }

    // fork: side stream does all weight transposes
    cudaEventRecord(evRoot, 0);
    cudaStreamWaitEvent(s1, evRoot, 0);
    transpose_qkvw<<<dim3(32, 32, 3), 256, 0, s1>>>(Wq, Wk, Wv, wqkvT);
    cudaEventRecord(evQkvW, s1);
    transpose_wo  <<<dim3(32, 32), 256, 0, s1>>>(Wo, woT);
    transpose_ffn <<<dim3(128, 32, 2), 256, 0, s1>>>(W1, W2, w1T, w2T);
    cudaEventRecord(evRestW, s1);

    // main stream: activation chain
    rmsnorm_h<<<NTOK, 256>>>(x, g1, xn);
    cudaStreamWaitEvent(0, evQkvW, 0);
    gemm_h<false, false, false, true><<<dim3(QKV_N / 128, NTOK / 128), 256, GEMM_SMEM>>>(
        xn, wqkvT, nullptr, nullptr, qkv, NTOK, QKV_N, D_MODEL);
    attn_h<<<dim3(T_SEQ / 64, NH, BATCH), 128, ATTN_SMEM>>>(qkv, attn);
    cudaStreamWaitEvent(0, evRestW, 0);
    gemm_h<false, false, true, false><<<dim3(D_MODEL / 128, NTOK / 128), 256, GEMM_SMEM>>>(
        attn, woT, nullptr, x, x2, NTOK, D_MODEL, D_MODEL);
    rmsnorm_h<<<NTOK, 256>>>(x2, g2, hn);
    gemm_h<true, true, false, true><<<dim3(D_FF / 128, NTOK / 128), 256, GEMM_SMEM>>>(
        hn, w1T, b1, nullptr, f1, NTOK, D_FF, D_MODEL);
    gemm_h<true, false, true, false><<<dim3(D_MODEL / 128, NTOK / 128), 256, GEMM_SMEM>>>(
        f1, w2T, b2, x2, out, NTOK, D_MODEL, D_FF);
}

// round 16
// speedup vs baseline: 1.0091x; 1.0091x over previous
#include <cuda_runtime.h>
#include <cuda_fp16.h>
#include <math.h>
#include <cstdint>

#define D_MODEL 1024
#define T_SEQ   2048
#define BATCH   2
#define NTOK    (BATCH * T_SEQ)   // 4096
#define D_FF    4096
#define NH      16
#define DH      64
#define QKV_N   3072

// ---------------- scratch (no allocations allowed) ----------------
__device__ __half g_xn_h  [NTOK * D_MODEL];
__device__ __half g_qkv_h [NTOK * QKV_N];
__device__ __half g_attn_h[NTOK * D_MODEL];
__device__ float  g_x2    [NTOK * D_MODEL];
__device__ __half g_hn_h  [NTOK * D_MODEL];
__device__ __half g_f1_h  [NTOK * D_FF];
__device__ __half g_wqkvT [QKV_N * D_MODEL];
__device__ __half g_woT   [D_MODEL * D_MODEL];
__device__ __half g_w1T   [D_FF * D_MODEL];
__device__ __half g_w2T   [D_MODEL * D_FF];

__device__ __forceinline__ uint32_t smem_u32(const void* p) {
    uint32_t a;
    asm("{ .reg .u64 t; cvta.to.shared.u64 t, %1; cvt.u32.u64 %0, t; }" : "=r"(a) : "l"(p));
    return a;
}
#define CP_ASYNC16(dst, src) \
    asm volatile("cp.async.cg.shared.global [%0], [%1], 16;" :: "r"(dst), "l"(src))
#define CP_COMMIT() asm volatile("cp.async.commit_group;")
#define CP_WAIT0()  asm volatile("cp.async.wait_group 0;")
#define CP_WAIT1()  asm volatile("cp.async.wait_group 1;")

#define MMA_F16(c0, c1, c2, c3, a0, a1, a2, a3, b0, b1) \
    asm volatile( \
        "mma.sync.aligned.m16n8k16.row.col.f32.f16.f16.f32 " \
        "{%0,%1,%2,%3}, {%4,%5,%6,%7}, {%8,%9}, {%0,%1,%2,%3};" \
        : "+f"(c0), "+f"(c1), "+f"(c2), "+f"(c3) \
        : "r"(a0), "r"(a1), "r"(a2), "r"(a3), "r"(b0), "r"(b1))

#define LDSM4(r0, r1, r2, r3, a) \
    asm volatile("ldmatrix.sync.aligned.m8n8.x4.shared.b16 {%0,%1,%2,%3}, [%4];" \
        : "=r"(r0), "=r"(r1), "=r"(r2), "=r"(r3) : "r"(a))
#define LDSM4T(r0, r1, r2, r3, a) \
    asm volatile("ldmatrix.sync.aligned.m8n8.x4.trans.shared.b16 {%0,%1,%2,%3}, [%4];" \
        : "=r"(r0), "=r"(r1), "=r"(r2), "=r"(r3) : "r"(a))

// ---------------- weight transposes: W[K][N] -> WT[N][K] (fp16) ----------------
__device__ __forceinline__ void trans_tile(
    const float* __restrict__ W, __half* __restrict__ WT, int K, int N, int n0, int k0)
{
    __shared__ float t[32][33];
    int tx = threadIdx.x & 31, ty = threadIdx.x >> 5;   // 32x8
    #pragma unroll
    for (int i = 0; i < 32; i += 8)
        t[ty + i][tx] = W[(size_t)(k0 + ty + i) * N + n0 + tx];
    __syncthreads();
    #pragma unroll
    for (int i = 0; i < 32; i += 8)
        WT[(size_t)(n0 + ty + i) * K + k0 + tx] = __float2half_rn(t[tx][ty + i]);
}

__global__ void __launch_bounds__(256) transpose_qkvw(
    const float* __restrict__ Wq, const float* __restrict__ Wk,
    const float* __restrict__ Wv, __half* __restrict__ qkvT)
{
    int z = blockIdx.z;
    const float* src = (z == 0) ? Wq : (z == 1) ? Wk : Wv;
    trans_tile(src, qkvT + (size_t)z * D_MODEL * D_MODEL,
               D_MODEL, D_MODEL, blockIdx.x * 32, blockIdx.y * 32);
}

__global__ void __launch_bounds__(256) transpose_wo(
    const float* __restrict__ Wo, __half* __restrict__ woT)
{
    trans_tile(Wo, woT, D_MODEL, D_MODEL, blockIdx.x * 32, blockIdx.y * 32);
}

__global__ void __launch_bounds__(256) transpose_ffn(
    const float* __restrict__ W1, const float* __restrict__ W2,
    __half* __restrict__ w1T, __half* __restrict__ w2T)
{
    if (blockIdx.z == 0)
        trans_tile(W1, w1T, D_MODEL, D_FF, blockIdx.x * 32, blockIdx.y * 32);
    else
        trans_tile(W2, w2T, D_FF, D_MODEL, blockIdx.y * 32, blockIdx.x * 32);
}

// ---------------- RMSNorm ----------------
__global__ void __launch_bounds__(256) rmsnorm_h(
    const float* __restrict__ x, const float* __restrict__ g, __half* __restrict__ y)
{
    int row = blockIdx.x;
    int tid = threadIdx.x;
    const float4* xr = (const float4*)(x + (size_t)row * D_MODEL);
    float4 v = xr[tid];
    float s = v.x * v.x + v.y * v.y + v.z * v.z + v.w * v.w;
    #pragma unroll
    for (int o = 16; o > 0; o >>= 1) s += __shfl_xor_sync(0xffffffffu, s, o);
    __shared__ float red[8];
    if ((tid & 31) == 0) red[tid >> 5] = s;
    __syncthreads();
    float tot = red[0] + red[1] + red[2] + red[3] + red[4] + red[5] + red[6] + red[7];
    float inv = rsqrtf(tot * (1.0f / D_MODEL) + 1e-6f);
    float4 gv = ((const float4*)g)[tid];
    __half2* yp = (__half2*)(y + (size_t)row * D_MODEL + tid * 4);
    yp[0] = __floats2half2_rn(v.x * inv * gv.x, v.y * inv * gv.y);
    yp[1] = __floats2half2_rn(v.z * inv * gv.z, v.w * inv * gv.w);
}

// ---------------- fp16 mma GEMM: R8 winner (3-stage cp.async + reg-pipelined frags) ----------
#define KC 64
#define HSTR 72
#define STAGE_HL (128 * HSTR)
#define STAGE_B  (STAGE_HL * 2)          // 18,432 bytes
#define GEMM_SMEM (3 * 2 * STAGE_B)      // 110,592 bytes

template<bool BIAS, bool GELU_ACT, bool RES, bool HOUT>
__global__ void __launch_bounds__(256) gemm_h(
    const __half* __restrict__ A, const __half* __restrict__ BT,
    const float* __restrict__ bias, const float* __restrict__ res,
    void* __restrict__ Cv, int M, int N, int K)
{
    extern __shared__ __half smh[];
    uint32_t AsU = smem_u32(smh);
    uint32_t BsU = AsU + 3 * STAGE_B;

    int tid = threadIdx.x;
    int lane = tid & 31, wid = tid >> 5;
    int warpM = (wid & 1) * 64;
    int warpN = (wid >> 1) * 32;
    int grp = lane >> 2, tig = lane & 3;
    int m8 = lane >> 3, l8 = lane & 7;
    int bn = blockIdx.x, bm = blockIdx.y;

    int ldrow = tid >> 3;                // 0..31, step 32
    int ldseg = (tid & 7) << 3;          // 0..56 halfs
    const __half* Aptr = A  + (size_t)bm * 128 * K + (size_t)ldrow * K + ldseg;
    const __half* Bptr = BT + (size_t)bn * 128 * K + (size_t)ldrow * K + ldseg;
    uint32_t dA = AsU + (uint32_t)(ldrow * HSTR + ldseg) * 2;
    uint32_t dB = BsU + (uint32_t)(ldrow * HSTR + ldseg) * 2;

    uint32_t aOff[4], bOff[2];
    #pragma unroll
    for (int mi = 0; mi < 4; mi++)
        aOff[mi] = (uint32_t)((warpM + mi * 16 + (lane & 15)) * HSTR
                              + ((lane >> 4) << 3)) * 2;
    #pragma unroll
    for (int j = 0; j < 2; j++)
        bOff[j] = (uint32_t)((warpN + j * 16 + ((m8 >> 1) << 3) + l8) * HSTR
                              + ((m8 & 1) << 3)) * 2;

    float acc[4][4][4];
    #pragma unroll
    for (int mi = 0; mi < 4; mi++)
        #pragma unroll
        for (int ni = 0; ni < 4; ni++)
            #pragma unroll
            for (int r = 0; r < 4; r++) acc[mi][ni][r] = 0.f;

    int nch = K / KC;

    #pragma unroll
    for (int s = 0; s < 2; s++) {
        uint32_t so = (uint32_t)s * STAGE_B;
        int k0 = s * KC;
        #pragma unroll
        for (int t = 0; t < 4; t++) {
            CP_ASYNC16(dA + so + (uint32_t)(t * 32 * HSTR) * 2,
                       Aptr + (size_t)t * 32 * K + k0);
            CP_ASYNC16(dB + so + (uint32_t)(t * 32 * HSTR) * 2,
                       Bptr + (size_t)t * 32 * K + k0);
        }
        CP_COMMIT();
    }

    uint32_t af[2][4][4], bf[2][4][2];

    int stage = 0;
    for (int c = 0; c < nch; c++) {
        if (c + 1 < nch) { CP_WAIT1(); } else { CP_WAIT0(); }
        __syncthreads();
        if (c + 2 < nch) {
            int sn = stage - 1; if (sn < 0) sn += 3;
            uint32_t so = (uint32_t)sn * STAGE_B;
            int k0 = (c + 2) * KC;
            #pragma unroll
            for (int t = 0; t < 4; t++) {
                CP_ASYNC16(dA + so + (uint32_t)(t * 32 * HSTR) * 2,
                           Aptr + (size_t)t * 32 * K + k0);
                CP_ASYNC16(dB + so + (uint32_t)(t * 32 * HSTR) * 2,
                           Bptr + (size_t)t * 32 * K + k0);
            }
            CP_COMMIT();
        }
        uint32_t abase = AsU + (uint32_t)stage * STAGE_B;
        uint32_t bbase = BsU + (uint32_t)stage * STAGE_B;

        #pragma unroll
        for (int mi = 0; mi < 4; mi++)
            LDSM4(af[0][mi][0], af[0][mi][1], af[0][mi][2], af[0][mi][3],
                  abase + aOff[mi]);
        #pragma unroll
        for (int j = 0; j < 2; j++)
            LDSM4(bf[0][2 * j][0], bf[0][2 * j][1], bf[0][2 * j + 1][0], bf[0][2 * j + 1][1],
                  bbase + bOff[j]);

        #pragma unroll
        for (int kk = 0; kk < 4; kk++) {
            int cur = kk & 1, nxt = cur ^ 1;
            if (kk < 3) {
                uint32_t kb = (uint32_t)(kk + 1) * 32;
                #pragma unroll
                for (int mi = 0; mi < 4; mi++)
                    LDSM4(af[nxt][mi][0], af[nxt][mi][1], af[nxt][mi][2], af[nxt][mi][3],
                          abase + aOff[mi] + kb);
                #pragma unroll
                for (int j = 0; j < 2; j++)
                    LDSM4(bf[nxt][2 * j][0], bf[nxt][2 * j][1],
                          bf[nxt][2 * j + 1][0], bf[nxt][2 * j + 1][1],
                          bbase + bOff[j] + kb);
            }
            #pragma unroll
            for (int mi = 0; mi < 4; mi++)
                #pragma unroll
                for (int ni = 0; ni < 4; ni++)
                    MMA_F16(acc[mi][ni][0], acc[mi][ni][1], acc[mi][ni][2], acc[mi][ni][3],
                            af[cur][mi][0], af[cur][mi][1], af[cur][mi][2], af[cur][mi][3],
                            bf[cur][ni][0], bf[cur][ni][1]);
        }
        stage++; if (stage == 3) stage = 0;
    }

    #pragma unroll
    for (int mi = 0; mi < 4; mi++) {
        #pragma unroll
        for (int half = 0; half < 2; half++) {
            size_t r = (size_t)bm * 128 + warpM + mi * 16 + grp + half * 8;
            #pragma unroll
            for (int ni = 0; ni < 4; ni++) {
                int cg = bn * 128 + warpN + ni * 8 + tig * 2;
                float v0 = acc[mi][ni][half * 2 + 0];
                float v1 = acc[mi][ni][half * 2 + 1];
                if (BIAS) { v0 += bias[cg]; v1 += bias[cg + 1]; }
                if (GELU_ACT) {
                    v0 = 0.5f * v0 * (1.0f + erff(v0 * 0.70710678118654752f));
                    v1 = 0.5f * v1 * (1.0f + erff(v1 * 0.70710678118654752f));
                }
                size_t idx = r * (size_t)N + cg;
                if (RES) {
                    float2 r2 = *(const float2*)(res + idx);
                    v0 += r2.x; v1 += r2.y;
                }
                if (HOUT) {
                    *(__half2*)((__half*)Cv + idx) = __floats2half2_rn(v0, v1);
                } else {
                    float2 o2; o2.x = v0; o2.y = v1;
                    *(float2*)((float*)Cv + idx) = o2;
                }
            }
        }
    }
}

// ---------------- fp16 mma causal flash attention: register P (no smem round-trip) --------
#define ASTR 72
#define Q_HL (64 * ASTR)
#define K_HL (64 * ASTR)
#define V_HL (64 * ASTR)
#define ATTN_SMEM ((Q_HL + 2 * K_HL + 2 * V_HL) * 2)
#define SCL2 0.18033688011112042f   // 0.125 * log2(e)

__global__ void __launch_bounds__(128) attn_h(
    const __half* __restrict__ qkv, __half* __restrict__ o)
{
    extern __shared__ __half smh[];
    __half* Qs = smh;
    __half* Ks = Qs + Q_HL;           // 2 buffers
    __half* Vs = Ks + 2 * K_HL;       // 2 buffers
    int tid = threadIdx.x;
    int lane = tid & 31, wid = tid >> 5;
    int grp = lane >> 2, tig = lane & 3;
    int m8 = lane >> 3, l8 = lane & 7;

    uint32_t QsU = smem_u32(Qs), KsU = smem_u32(Ks), VsU = smem_u32(Vs);

    int qb = gridDim.x - 1 - blockIdx.x;   // heavy tiles first
    int h = blockIdx.y, b = blockIdx.z;
    size_t base  = (size_t)b * T_SEQ * QKV_N + h * DH;
    size_t baseo = (size_t)b * T_SEQ * D_MODEL + h * DH;
    const __half* qg = qkv + base;
    const __half* kg = qkv + base + D_MODEL;
    const __half* vg = qkv + base + 2 * D_MODEL;

    uint32_t qOff = (uint32_t)((wid * 16 + (lane & 15)) * ASTR + ((lane >> 4) << 3)) * 2;
    uint32_t kOff[4], vOff[4];
    #pragma unroll
    for (int j = 0; j < 4; j++) {
        kOff[j] = (uint32_t)((j * 16 + ((m8 >> 1) << 3) + l8) * ASTR
                             + ((m8 & 1) << 3)) * 2;
        vOff[j] = (uint32_t)((((m8 & 1) << 3) + l8) * ASTR
                             + j * 16 + ((m8 >> 1) << 3)) * 2;
    }

    int ldrow = tid >> 3, ldseg = (tid & 7) << 3;   // 16 rows/step

    #pragma unroll
    for (int t = 0; t < 4; t++) {
        int r = ldrow + t * 16;
        CP_ASYNC16(QsU + (uint32_t)(r * ASTR + ldseg) * 2,
                   qg + (size_t)(qb * 64 + r) * QKV_N + ldseg);
    }
    #pragma unroll
    for (int t = 0; t < 4; t++) {
        int r = ldrow + t * 16;
        CP_ASYNC16(KsU + (uint32_t)(r * ASTR + ldseg) * 2, kg + (size_t)r * QKV_N + ldseg);
        CP_ASYNC16(VsU + (uint32_t)(r * ASTR + ldseg) * 2, vg + (size_t)r * QKV_N + ldseg);
    }
    CP_COMMIT();

    float m0 = -1e30f, m1 = -1e30f, l0 = 0.f, l1 = 0.f;
    float oa[8][4];
    #pragma unroll
    for (int ni = 0; ni < 8; ni++)
        #pragma unroll
        for (int r = 0; r < 4; r++) oa[ni][r] = 0.f;

    int row_l0 = wid * 16 + grp;
    int row_l1 = row_l0 + 8;

    for (int kb = 0; kb <= qb; kb++) {
        CP_WAIT0();
        __syncthreads();
        if (kb < qb) {
            uint32_t kbuf = KsU + (uint32_t)(((kb + 1) & 1) * K_HL) * 2;
            uint32_t vbuf = VsU + (uint32_t)(((kb + 1) & 1) * V_HL) * 2;
            const __half* kgn = kg + (size_t)(kb + 1) * 64 * QKV_N;
            const __half* vgn = vg + (size_t)(kb + 1) * 64 * QKV_N;
            #pragma unroll
            for (int t = 0; t < 4; t++) {
                int r = ldrow + t * 16;
                CP_ASYNC16(kbuf + (uint32_t)(r * ASTR + ldseg) * 2,
                           kgn + (size_t)r * QKV_N + ldseg);
                CP_ASYNC16(vbuf + (uint32_t)(r * ASTR + ldseg) * 2,
                           vgn + (size_t)r * QKV_N + ldseg);
            }
            CP_COMMIT();
        }
        uint32_t kcur = KsU + (uint32_t)((kb & 1) * K_HL) * 2;
        uint32_t vcur = VsU + (uint32_t)((kb & 1) * V_HL) * 2;

        // S = Q @ K^T (f32 accumulate)
        float s[8][4];
        #pragma unroll
        for (int ni = 0; ni < 8; ni++)
            #pragma unroll
            for (int r = 0; r < 4; r++) s[ni][r] = 0.f;
        #pragma unroll
        for (int ks = 0; ks < 4; ks++) {
            uint32_t kbyte = (uint32_t)ks * 32;
            uint32_t a0, a1, a2, a3;
            LDSM4(a0, a1, a2, a3, QsU + qOff + kbyte);
            uint32_t bfr[8][2];
            #pragma unroll
            for (int j = 0; j < 4; j++)
                LDSM4(bfr[2 * j][0], bfr[2 * j][1], bfr[2 * j + 1][0], bfr[2 * j + 1][1],
                      kcur + kOff[j] + kbyte);
            #pragma unroll
            for (int ni = 0; ni < 8; ni++)
                MMA_F16(s[ni][0], s[ni][1], s[ni][2], s[ni][3],
                        a0, a1, a2, a3, bfr[ni][0], bfr[ni][1]);
        }
        #pragma unroll
        for (int ni = 0; ni < 8; ni++)
            #pragma unroll
            for (int r = 0; r < 4; r++) s[ni][r] *= SCL2;
        if (kb == qb) {
            #pragma unroll
            for (int ni = 0; ni < 8; ni++) {
                int c0 = ni * 8 + tig * 2, c1 = c0 + 1;
                if (c0 > row_l0) s[ni][0] = -1e30f;
                if (c1 > row_l0) s[ni][1] = -1e30f;
                if (c0 > row_l1) s[ni][2] = -1e30f;
                if (c1 > row_l1) s[ni][3] = -1e30f;
            }
        }

        float rm0 = -1e30f, rm1 = -1e30f;
        #pragma unroll
        for (int ni = 0; ni < 8; ni++) {
            rm0 = fmaxf(rm0, fmaxf(s[ni][0], s[ni][1]));
            rm1 = fmaxf(rm1, fmaxf(s[ni][2], s[ni][3]));
        }
        rm0 = fmaxf(rm0, __shfl_xor_sync(0xffffffffu, rm0, 1));
        rm0 = fmaxf(rm0, __shfl_xor_sync(0xffffffffu, rm0, 2));
        rm1 = fmaxf(rm1, __shfl_xor_sync(0xffffffffu, rm1, 1));
        rm1 = fmaxf(rm1, __shfl_xor_sync(0xffffffffu, rm1, 2));
        float mn0 = fmaxf(m0, rm0), mn1 = fmaxf(m1, rm1);
        float al0 = exp2f(m0 - mn0), al1 = exp2f(m1 - mn1);
        float rs0 = 0.f, rs1 = 0.f;
        uint32_t ph[8][2];   // P packed as PV A-fragments (fragment-layout identity)
        #pragma unroll
        for (int ni = 0; ni < 8; ni++) {
            s[ni][0] = exp2f(s[ni][0] - mn0); rs0 += s[ni][0];
            s[ni][1] = exp2f(s[ni][1] - mn0); rs0 += s[ni][1];
            s[ni][2] = exp2f(s[ni][2] - mn1); rs1 += s[ni][2];
            s[ni][3] = exp2f(s[ni][3] - mn1); rs1 += s[ni][3];
            __half2 p01 = __floats2half2_rn(s[ni][0], s[ni][1]);
            __half2 p23 = __floats2half2_rn(s[ni][2], s[ni][3]);
            ph[ni][0] = *(uint32_t*)&p01;
            ph[ni][1] = *(uint32_t*)&p23;
        }
        rs0 += __shfl_xor_sync(0xffffffffu, rs0, 1);
        rs0 += __shfl_xor_sync(0xffffffffu, rs0, 2);
        rs1 += __shfl_xor_sync(0xffffffffu, rs1, 1);
        rs1 += __shfl_xor_sync(0xffffffffu, rs1, 2);
        l0 = l0 * al0 + rs0; l1 = l1 * al1 + rs1;
        m0 = mn0; m1 = mn1;
        #pragma unroll
        for (int ni = 0; ni < 8; ni++) {
            oa[ni][0] *= al0; oa[ni][1] *= al0;
            oa[ni][2] *= al1; oa[ni][3] *= al1;
        }

        // O += P @ V : P fed straight from registers (S-frag == A-frag layout)
        #pragma unroll
        for (int ks = 0; ks < 4; ks++) {
            uint32_t a0 = ph[2 * ks][0], a1 = ph[2 * ks][1];
            uint32_t a2 = ph[2 * ks + 1][0], a3 = ph[2 * ks + 1][1];
            uint32_t vrow = (uint32_t)(ks * 16 * ASTR) * 2;
            uint32_t bfr[8][2];
            #pragma unroll
            for (int j = 0; j < 4; j++)
                LDSM4T(bfr[2 * j][0], bfr[2 * j][1], bfr[2 * j + 1][0], bfr[2 * j + 1][1],
                       vcur + vrow + vOff[j]);
            #pragma unroll
            for (int ni = 0; ni < 8; ni++)
                MMA_F16(oa[ni][0], oa[ni][1], oa[ni][2], oa[ni][3],
                        a0, a1, a2, a3, bfr[ni][0], bfr[ni][1]);
        }
    }

    float inv0 = 1.f / l0, inv1 = 1.f / l1;
    size_t r0 = baseo + (size_t)(qb * 64 + row_l0) * D_MODEL;
    size_t r1 = baseo + (size_t)(qb * 64 + row_l1) * D_MODEL;
    #pragma unroll
    for (int ni = 0; ni < 8; ni++) {
        int cc = ni * 8 + tig * 2;
        *(__half2*)(o + r0 + cc) = __floats2half2_rn(oa[ni][0] * inv0, oa[ni][1] * inv0);
        *(__half2*)(o + r1 + cc) = __floats2half2_rn(oa[ni][2] * inv1, oa[ni][3] * inv1);
    }
}

// ---------------- launch (dual-stream: transposes overlap the activation chain) --------
extern "C" void kernel_launch(void* const* d_in, const int* in_sizes, int n_in,
                              void* d_out, int out_size)
{
    const float* x  = (const float*)d_in[0];
    const float* Wq = (const float*)d_in[1];
    const float* Wk = (const float*)d_in[2];
    const float* Wv = (const float*)d_in[3];
    const float* Wo = (const float*)d_in[4];
    const float* W1 = (const float*)d_in[5];
    const float* b1 = (const float*)d_in[6];
    const float* W2 = (const float*)d_in[7];
    const float* b2 = (const float*)d_in[8];
    const float* g1 = (const float*)d_in[9];
    const float* g2 = (const float*)d_in[10];
    float* out = (float*)d_out;

    __half *xn, *qkv, *attn, *hn, *f1, *wqkvT, *woT, *w1T, *w2T;
    float* x2;
    cudaGetSymbolAddress((void**)&xn,    g_xn_h);
    cudaGetSymbolAddress((void**)&qkv,   g_qkv_h);
    cudaGetSymbolAddress((void**)&attn,  g_attn_h);
    cudaGetSymbolAddress((void**)&x2,    g_x2);
    cudaGetSymbolAddress((void**)&hn,    g_hn_h);
    cudaGetSymbolAddress((void**)&f1,    g_f1_h);
    cudaGetSymbolAddress((void**)&wqkvT, g_wqkvT);
    cudaGetSymbolAddress((void**)&woT,   g_woT);
    cudaGetSymbolAddress((void**)&w1T,   g_w1T);
    cudaGetSymbolAddress((void**)&w2T,   g_w2T);

    cudaFuncSetAttribute(gemm_h<false, false, false, true>,
                         cudaFuncAttributeMaxDynamicSharedMemorySize, GEMM_SMEM);
    cudaFuncSetAttribute(gemm_h<false, false, true, false>,
                         cudaFuncAttributeMaxDynamicSharedMemorySize, GEMM_SMEM);
    cudaFuncSetAttribute(gemm_h<true, true, false, true>,
                         cudaFuncAttributeMaxDynamicSharedMemorySize, GEMM_SMEM);
    cudaFuncSetAttribute(gemm_h<true, false, true, false>,
                         cudaFuncAttributeMaxDynamicSharedMemorySize, GEMM_SMEM);
    cudaFuncSetAttribute(attn_h, cudaFuncAttributeMaxDynamicSharedMemorySize, ATTN_SMEM);

    // static side-stream + events (created on the first, uncaptured, call)
    static cudaStream_t s1 = nullptr;
    static cudaEvent_t evRoot = nullptr, evQkvW = nullptr, evRestW = nullptr;
    if (!s1) {
        cudaStreamCreateWithFlags(&s1, cudaStreamNonBlocking);
        cudaEventCreateWithFlags(&evRoot,  cudaEventDisableTiming);
        cudaEventCreateWithFlags(&evQkvW,  cudaEventDisableTiming);
        cudaEventCreateWithFlags(&evRestW, cudaEventDisableTiming);
    }

    // fork: side stream does all weight transposes
    cudaEventRecord(evRoot, 0);
    cudaStreamWaitEvent(s1, evRoot, 0);
    transpose_qkvw<<<dim3(32, 32, 3), 256, 0, s1>>>(Wq, Wk, Wv, wqkvT);
    cudaEventRecord(evQkvW, s1);
    transpose_wo  <<<dim3(32, 32), 256, 0, s1>>>(Wo, woT);
    transpose_ffn <<<dim3(128, 32, 2), 256, 0, s1>>>(W1, W2, w1T, w2T);
    cudaEventRecord(evRestW, s1);

    // main stream: activation chain
    rmsnorm_h<<<NTOK, 256>>>(x, g1, xn);
    cudaStreamWaitEvent(0, evQkvW, 0);
    gemm_h<false, false, false, true><<<dim3(QKV_N / 128, NTOK / 128), 256, GEMM_SMEM>>>(
        xn, wqkvT, nullptr, nullptr, qkv, NTOK, QKV_N, D_MODEL);
    attn_h<<<dim3(T_SEQ / 64, NH, BATCH), 128, ATTN_SMEM>>>(qkv, attn);
    cudaStreamWaitEvent(0, evRestW, 0);
    gemm_h<false, false, true, false><<<dim3(D_MODEL / 128, NTOK / 128), 256, GEMM_SMEM>>>(
        attn, woT, nullptr, x, x2, NTOK, D_MODEL, D_MODEL);
    rmsnorm_h<<<NTOK, 256>>>(x2, g2, hn);
    gemm_h<true, true, false, true><<<dim3(D_FF / 128, NTOK / 128), 256, GEMM_SMEM>>>(
        hn, w1T, b1, nullptr, f1, NTOK, D_FF, D_MODEL);
    gemm_h<true, false, true, false><<<dim3(D_MODEL / 128, NTOK / 128), 256, GEMM_SMEM>>>(
        f1, w2T, b2, x2, out, NTOK, D_MODEL, D_FF);
}